// round 2
// baseline (speedup 1.0000x reference)
#include <cuda_runtime.h>
#include <math.h>

#define BB   256   // batch
#define CC   256   // channels
#define TT   256   // tokens (16x16)
#define NH   8
#define HD   32
#define META 256
#define OC3  768

// ---------------- scratch (device globals; no runtime allocation) ----------
__device__ float g_q[(size_t)BB * NH * TT * HD];     // 64 MB  [b][h][t][d]
__device__ float g_k[(size_t)BB * NH * TT * HD];     // 64 MB
__device__ float g_v[(size_t)BB * NH * TT * HD];     // 64 MB
__device__ float g_ao[(size_t)BB * CC * TT];         // 64 MB  [b][c][t]
__device__ float g_biasT[(size_t)NH * TT * TT];      // 2 MB   [h][key][query]

// ---------------------------------------------------------------------------
// Kernel 1: relative-position-bias MLP.  bias[h,q,k] stored transposed as
// g_biasT[h][k][q] so the attention loop (thread==query) reads coalesced.
// ---------------------------------------------------------------------------
__global__ __launch_bounds__(256) void bias_kernel(
    const float* __restrict__ mw1, const float* __restrict__ mb1,
    const float* __restrict__ mw2, const float* __restrict__ mb2)
{
    __shared__ float s_w1[META * 2];
    __shared__ float s_b1[META];
    __shared__ float s_w2[NH * META];
    __shared__ float s_b2[NH];
    for (int i = threadIdx.x; i < META * 2; i += 256) s_w1[i] = mw1[i];
    for (int i = threadIdx.x; i < META;     i += 256) s_b1[i] = mb1[i];
    for (int i = threadIdx.x; i < NH * META; i += 256) s_w2[i] = mw2[i];
    if (threadIdx.x < NH) s_b2[threadIdx.x] = mb2[threadIdx.x];
    __syncthreads();

    int idx = blockIdx.x * 256 + threadIdx.x;   // idx = kk*T + q  (q fast)
    int q  = idx & (TT - 1);
    int kk = idx >> 8;

    float d0 = (float)((q >> 4) - (kk >> 4));
    float d1 = (float)((q & 15) - (kk & 15));
    float r0 = copysignf(log1pf(fabsf(d0)), d0);
    float r1 = copysignf(log1pf(fabsf(d1)), d1);

    float acc[NH];
#pragma unroll
    for (int h = 0; h < NH; h++) acc[h] = s_b2[h];

    for (int j = 0; j < META; j++) {
        float hj = fmaf(r0, s_w1[2 * j], fmaf(r1, s_w1[2 * j + 1], s_b1[j]));
        hj = fmaxf(hj, 0.0f);
#pragma unroll
        for (int h = 0; h < NH; h++)
            acc[h] = fmaf(hj, s_w2[h * META + j], acc[h]);
    }
#pragma unroll
    for (int h = 0; h < NH; h++)
        g_biasT[(size_t)h * TT * TT + (size_t)kk * TT + q] = acc[h];
}

// ---------------------------------------------------------------------------
// Kernel 2: QKV GEMM.  qkv[b,t,oc] = sum_c x[b,c,t] * w[oc,c] + b[oc]
// A is the transposed view of x ([b][c][t], contiguous in t) -> As[k][m].
// Output scattered directly into g_q/g_k/g_v in [b][h][t][d] layout.
// ---------------------------------------------------------------------------
#define GBM 64
#define GBN 64
#define GBK 32
#define BKP 36   // padded k-stride for Bs: 144B rows keep float4 alignment,
                 // conflict-free transposed stores

__global__ __launch_bounds__(256) void qkv_kernel(
    const float* __restrict__ x, const float* __restrict__ w,
    const float* __restrict__ bq)
{
    __shared__ float As[GBK * GBM];   // [k][m]
    __shared__ float Bs[GBN * BKP];   // [n][k+pad]

    const int tid = threadIdx.x;
    const int tx = tid & 15;          // m group (4 rows each)
    const int ty = tid >> 4;          // n group (4 cols each)
    const int m0 = blockIdx.y * GBM;
    const int n0 = blockIdx.x * GBN;
    const int b  = m0 >> 8;           // tile never crosses a batch (64 | 256)
    const int t0 = m0 & (TT - 1);
    const float* xb = x + (size_t)b * CC * TT;

    float acc[4][4];
#pragma unroll
    for (int i = 0; i < 4; i++)
#pragma unroll
        for (int j = 0; j < 4; j++) acc[i][j] = 0.0f;

    for (int k0 = 0; k0 < CC; k0 += GBK) {
        // A tile: 32(k) x 64(t), float4 along t (coalesced)
#pragma unroll
        for (int s = 0; s < 2; s++) {
            int item = tid + s * 256;
            int kk = item >> 4;
            int t4 = item & 15;
            float4 v4 = *(const float4*)(xb + (size_t)(k0 + kk) * TT + t0 + t4 * 4);
            *(float4*)(As + kk * GBM + t4 * 4) = v4;
        }
        // B tile: 64(n) x 32(k), float4 along k (coalesced)
#pragma unroll
        for (int s = 0; s < 2; s++) {
            int item = tid + s * 256;
            int n  = item >> 3;
            int k4 = item & 7;
            float4 v4 = *(const float4*)(w + (size_t)(n0 + n) * CC + k0 + k4 * 4);
            *(float4*)(Bs + n * BKP + k4 * 4) = v4;
        }
        __syncthreads();

#pragma unroll
        for (int k = 0; k < GBK; k++) {
            float4 a4 = *(const float4*)(As + k * GBM + tx * 4);
            float b0 = Bs[(ty * 4 + 0) * BKP + k];
            float b1 = Bs[(ty * 4 + 1) * BKP + k];
            float b2 = Bs[(ty * 4 + 2) * BKP + k];
            float b3 = Bs[(ty * 4 + 3) * BKP + k];
            acc[0][0] = fmaf(a4.x, b0, acc[0][0]);
            acc[0][1] = fmaf(a4.x, b1, acc[0][1]);
            acc[0][2] = fmaf(a4.x, b2, acc[0][2]);
            acc[0][3] = fmaf(a4.x, b3, acc[0][3]);
            acc[1][0] = fmaf(a4.y, b0, acc[1][0]);
            acc[1][1] = fmaf(a4.y, b1, acc[1][1]);
            acc[1][2] = fmaf(a4.y, b2, acc[1][2]);
            acc[1][3] = fmaf(a4.y, b3, acc[1][3]);
            acc[2][0] = fmaf(a4.z, b0, acc[2][0]);
            acc[2][1] = fmaf(a4.z, b1, acc[2][1]);
            acc[2][2] = fmaf(a4.z, b2, acc[2][2]);
            acc[2][3] = fmaf(a4.z, b3, acc[2][3]);
            acc[3][0] = fmaf(a4.w, b0, acc[3][0]);
            acc[3][1] = fmaf(a4.w, b1, acc[3][1]);
            acc[3][2] = fmaf(a4.w, b2, acc[3][2]);
            acc[3][3] = fmaf(a4.w, b3, acc[3][3]);
        }
        __syncthreads();
    }

    // Epilogue: oc group of 4 is 4-aligned and never crosses a 32-wide head
    const int oc0 = n0 + ty * 4;
    const int s   = oc0 >> 8;          // 0=q 1=k 2=v
    const int ch  = oc0 & (CC - 1);
    const int h   = ch >> 5;
    const int d0  = ch & (HD - 1);
    float4 bb = *(const float4*)(bq + oc0);
    float* dst = (s == 0) ? g_q : (s == 1) ? g_k : g_v;
    dst += (((size_t)b * NH + h) * TT) * HD + d0;
#pragma unroll
    for (int i = 0; i < 4; i++) {
        int t = t0 + tx * 4 + i;
        float4 o;
        o.x = acc[i][0] + bb.x;
        o.y = acc[i][1] + bb.y;
        o.z = acc[i][2] + bb.z;
        o.w = acc[i][3] + bb.w;
        *(float4*)(dst + (size_t)t * HD) = o;
    }
}

// ---------------------------------------------------------------------------
// Kernel 3: attention.  One block per (b,h); one query per thread.
// Cosine-sim scores + bias, online softmax, K/V staged in 2x128-key smem tiles.
// Writes out in [b][c][t] layout (so proj == same GEMM shape as QKV).
// ---------------------------------------------------------------------------
#define KSTAGE 128
#define KP     36

__global__ __launch_bounds__(256) void attn_kernel(const float* __restrict__ tau)
{
    __shared__ float ks[KSTAGE * KP];
    __shared__ float vs[KSTAGE * KP];
    __shared__ float kn[KSTAGE];

    const int tid = threadIdx.x;
    const int bh  = blockIdx.x;
    const int b   = bh >> 3;
    const int h   = bh & 7;
    const size_t base = (size_t)bh * TT * HD;

    // own query row -> registers (one 128B line per thread, fully used)
    float q[HD];
    {
        const float4* qr = (const float4*)(g_q + base + (size_t)tid * HD);
#pragma unroll
        for (int d4 = 0; d4 < 8; d4++) {
            float4 t4 = qr[d4];
            q[4 * d4 + 0] = t4.x; q[4 * d4 + 1] = t4.y;
            q[4 * d4 + 2] = t4.z; q[4 * d4 + 3] = t4.w;
        }
    }
    float qn = 0.0f;
#pragma unroll
    for (int d = 0; d < HD; d++) qn = fmaf(q[d], q[d], qn);
    qn = sqrtf(qn);
    const float inv_tau = 1.0f / fmaxf(tau[h], 0.01f);
    const float* brow = g_biasT + (size_t)h * TT * TT + tid;

    float m = -1e30f, l = 0.0f;
    float acc[HD];
#pragma unroll
    for (int d = 0; d < HD; d++) acc[d] = 0.0f;

    for (int j0 = 0; j0 < TT; j0 += KSTAGE) {
        __syncthreads();
        // stage K/V (coalesced)
        const float* kg = g_k + base + (size_t)j0 * HD;
        const float* vg = g_v + base + (size_t)j0 * HD;
        for (int i = tid; i < KSTAGE * HD; i += 256) {
            int r = i >> 5, c = i & 31;
            ks[r * KP + c] = kg[i];
            vs[r * KP + c] = vg[i];
        }
        __syncthreads();
        if (tid < KSTAGE) {
            float s2 = 0.0f;
#pragma unroll
            for (int d = 0; d < HD; d++) {
                float kv = ks[tid * KP + d];
                s2 = fmaf(kv, kv, s2);
            }
            kn[tid] = sqrtf(s2);
        }
        __syncthreads();

        for (int j = 0; j < KSTAGE; j++) {
            const float4* kr = (const float4*)(ks + j * KP);
            float p0 = 0.f, p1 = 0.f, p2 = 0.f, p3 = 0.f;
#pragma unroll
            for (int d4 = 0; d4 < 8; d4++) {
                float4 kv = kr[d4];
                p0 = fmaf(q[4 * d4 + 0], kv.x, p0);
                p1 = fmaf(q[4 * d4 + 1], kv.y, p1);
                p2 = fmaf(q[4 * d4 + 2], kv.z, p2);
                p3 = fmaf(q[4 * d4 + 3], kv.w, p3);
            }
            float dot = (p0 + p1) + (p2 + p3);
            float sc = dot / fmaxf(qn * kn[j], 1e-6f);
            sc = fmaf(sc, inv_tau, brow[(size_t)(j0 + j) * TT]);

            const float4* vr = (const float4*)(vs + j * KP);
            if (sc > m) {
                float r = __expf(m - sc);
                m = sc;
                l = fmaf(l, r, 1.0f);
#pragma unroll
                for (int d4 = 0; d4 < 8; d4++) {
                    float4 vv = vr[d4];
                    acc[4 * d4 + 0] = fmaf(acc[4 * d4 + 0], r, vv.x);
                    acc[4 * d4 + 1] = fmaf(acc[4 * d4 + 1], r, vv.y);
                    acc[4 * d4 + 2] = fmaf(acc[4 * d4 + 2], r, vv.z);
                    acc[4 * d4 + 3] = fmaf(acc[4 * d4 + 3], r, vv.w);
                }
            } else {
                float p = __expf(sc - m);
                l += p;
#pragma unroll
                for (int d4 = 0; d4 < 8; d4++) {
                    float4 vv = vr[d4];
                    acc[4 * d4 + 0] = fmaf(p, vv.x, acc[4 * d4 + 0]);
                    acc[4 * d4 + 1] = fmaf(p, vv.y, acc[4 * d4 + 1]);
                    acc[4 * d4 + 2] = fmaf(p, vv.z, acc[4 * d4 + 2]);
                    acc[4 * d4 + 3] = fmaf(p, vv.w, acc[4 * d4 + 3]);
                }
            }
        }
    }

    const float inv_l = 1.0f / l;
    float* ob = g_ao + ((size_t)b * CC + h * HD) * TT + tid;
#pragma unroll
    for (int d = 0; d < HD; d++)
        ob[(size_t)d * TT] = acc[d] * inv_l;   // coalesced per d
}

// ---------------------------------------------------------------------------
// Kernel 4: proj GEMM.  out[b,co,t] = sum_ci ao[b,ci,t]*w[co,ci] + b[co]
// Same structure as qkv_kernel (A = [b][k][t]); writes final output directly.
// ---------------------------------------------------------------------------
__global__ __launch_bounds__(256) void proj_kernel(
    const float* __restrict__ w, const float* __restrict__ bp,
    float* __restrict__ out)
{
    __shared__ float As[GBK * GBM];
    __shared__ float Bs[GBN * BKP];

    const int tid = threadIdx.x;
    const int tx = tid & 15;
    const int ty = tid >> 4;
    const int m0 = blockIdx.y * GBM;
    const int n0 = blockIdx.x * GBN;
    const int b  = m0 >> 8;
    const int t0 = m0 & (TT - 1);
    const float* ab = g_ao + (size_t)b * CC * TT;

    float acc[4][4];
#pragma unroll
    for (int i = 0; i < 4; i++)
#pragma unroll
        for (int j = 0; j < 4; j++) acc[i][j] = 0.0f;

    for (int k0 = 0; k0 < CC; k0 += GBK) {
#pragma unroll
        for (int s = 0; s < 2; s++) {
            int item = tid + s * 256;
            int kk = item >> 4;
            int t4 = item & 15;
            float4 v4 = *(const float4*)(ab + (size_t)(k0 + kk) * TT + t0 + t4 * 4);
            *(float4*)(As + kk * GBM + t4 * 4) = v4;
        }
#pragma unroll
        for (int s = 0; s < 2; s++) {
            int item = tid + s * 256;
            int n  = item >> 3;
            int k4 = item & 7;
            float4 v4 = *(const float4*)(w + (size_t)(n0 + n) * CC + k0 + k4 * 4);
            *(float4*)(Bs + n * BKP + k4 * 4) = v4;
        }
        __syncthreads();

#pragma unroll
        for (int k = 0; k < GBK; k++) {
            float4 a4 = *(const float4*)(As + k * GBM + tx * 4);
            float b0 = Bs[(ty * 4 + 0) * BKP + k];
            float b1 = Bs[(ty * 4 + 1) * BKP + k];
            float b2 = Bs[(ty * 4 + 2) * BKP + k];
            float b3 = Bs[(ty * 4 + 3) * BKP + k];
            acc[0][0] = fmaf(a4.x, b0, acc[0][0]);
            acc[0][1] = fmaf(a4.x, b1, acc[0][1]);
            acc[0][2] = fmaf(a4.x, b2, acc[0][2]);
            acc[0][3] = fmaf(a4.x, b3, acc[0][3]);
            acc[1][0] = fmaf(a4.y, b0, acc[1][0]);
            acc[1][1] = fmaf(a4.y, b1, acc[1][1]);
            acc[1][2] = fmaf(a4.y, b2, acc[1][2]);
            acc[1][3] = fmaf(a4.y, b3, acc[1][3]);
            acc[2][0] = fmaf(a4.z, b0, acc[2][0]);
            acc[2][1] = fmaf(a4.z, b1, acc[2][1]);
            acc[2][2] = fmaf(a4.z, b2, acc[2][2]);
            acc[2][3] = fmaf(a4.z, b3, acc[2][3]);
            acc[3][0] = fmaf(a4.w, b0, acc[3][0]);
            acc[3][1] = fmaf(a4.w, b1, acc[3][1]);
            acc[3][2] = fmaf(a4.w, b2, acc[3][2]);
            acc[3][3] = fmaf(a4.w, b3, acc[3][3]);
        }
        __syncthreads();
    }

    // out[b][n][t]: float4 along t (transpose of acc micro-tile)
#pragma unroll
    for (int j = 0; j < 4; j++) {
        int n = n0 + ty * 4 + j;
        float bpv = bp[n];
        float4 o;
        o.x = acc[0][j] + bpv;
        o.y = acc[1][j] + bpv;
        o.z = acc[2][j] + bpv;
        o.w = acc[3][j] + bpv;
        *(float4*)(out + ((size_t)b * CC + n) * TT + t0 + tx * 4) = o;
    }
}

// ---------------------------------------------------------------------------
extern "C" void kernel_launch(void* const* d_in, const int* in_sizes, int n_in,
                              void* d_out, int out_size)
{
    const float* x      = (const float*)d_in[0];
    const float* w_qkv  = (const float*)d_in[1];
    const float* b_qkv  = (const float*)d_in[2];
    const float* w_proj = (const float*)d_in[3];
    const float* b_proj = (const float*)d_in[4];
    const float* mw1    = (const float*)d_in[5];
    const float* mb1    = (const float*)d_in[6];
    const float* mw2    = (const float*)d_in[7];
    const float* mb2    = (const float*)d_in[8];
    const float* tau    = (const float*)d_in[9];
    float* out = (float*)d_out;

    bias_kernel<<<TT * TT / 256, 256>>>(mw1, mb1, mw2, mb2);
    qkv_kernel<<<dim3(OC3 / GBN, BB * TT / GBM), 256>>>(x, w_qkv, b_qkv);
    attn_kernel<<<BB * NH, 256>>>(tau);
    proj_kernel<<<dim3(CC / GBN, BB * TT / GBM), 256>>>(w_proj, b_proj, out);
}

// round 4
// speedup vs baseline: 1.2869x; 1.2869x over previous
#include <cuda_runtime.h>
#include <math.h>

#define BB   256   // batch
#define CC   256   // channels
#define TT   256   // tokens (16x16)
#define NH   8
#define HD   32
#define META 256
#define OC3  768

// ---------------- scratch (device globals; no runtime allocation) ----------
__device__ float g_q[(size_t)BB * NH * TT * HD];     // [b][h][t][d], pre-scaled by 1/(|q| tau)
__device__ float g_k[(size_t)BB * NH * TT * HD];
__device__ float g_v[(size_t)BB * NH * TT * HD];
__device__ float g_ao[(size_t)BB * CC * TT];         // [b][c][t]
__device__ float g_biasT[(size_t)NH * TT * TT];      // [h][key][query]

// ---------------------------------------------------------------------------
// Kernel 1: relative-position-bias MLP (transposed store: [h][key][query])
// ---------------------------------------------------------------------------
__global__ __launch_bounds__(256) void bias_kernel(
    const float* __restrict__ mw1, const float* __restrict__ mb1,
    const float* __restrict__ mw2, const float* __restrict__ mb2)
{
    __shared__ float s_w1[META * 2];
    __shared__ float s_b1[META];
    __shared__ float s_w2[NH * META];
    __shared__ float s_b2[NH];
    for (int i = threadIdx.x; i < META * 2; i += 256) s_w1[i] = mw1[i];
    for (int i = threadIdx.x; i < META;     i += 256) s_b1[i] = mb1[i];
    for (int i = threadIdx.x; i < NH * META; i += 256) s_w2[i] = mw2[i];
    if (threadIdx.x < NH) s_b2[threadIdx.x] = mb2[threadIdx.x];
    __syncthreads();

    int idx = blockIdx.x * 256 + threadIdx.x;   // idx = key*T + q  (q fast)
    int q  = idx & (TT - 1);
    int kk = idx >> 8;

    float d0 = (float)((q >> 4) - (kk >> 4));
    float d1 = (float)((q & 15) - (kk & 15));
    float r0 = copysignf(log1pf(fabsf(d0)), d0);
    float r1 = copysignf(log1pf(fabsf(d1)), d1);

    float acc[NH];
#pragma unroll
    for (int h = 0; h < NH; h++) acc[h] = s_b2[h];

    for (int j = 0; j < META; j++) {
        float hj = fmaf(r0, s_w1[2 * j], fmaf(r1, s_w1[2 * j + 1], s_b1[j]));
        hj = fmaxf(hj, 0.0f);
#pragma unroll
        for (int h = 0; h < NH; h++)
            acc[h] = fmaf(hj, s_w2[h * META + j], acc[h]);
    }
#pragma unroll
    for (int h = 0; h < NH; h++)
        g_biasT[(size_t)h * TT * TT + (size_t)kk * TT + q] = acc[h];
}

// ---------------------------------------------------------------------------
// GEMM tiles: 128(m) x 128(n) x 16(k), 256 threads, 8x8 micro-tile
// ---------------------------------------------------------------------------
#define GBM 128
#define GBN 128
#define GBK 16
#define BNP 132   // padded n-stride for Bs (transposed stores -> <=2-way conflict)

// Kernel 2: QKV GEMM.  qkv[b,t,oc] = sum_c x[b,c,t] * w[oc,c] + b[oc]
// q rows are pre-scaled by rsqrt(|q|^2)/tau in the epilogue.
__global__ __launch_bounds__(256, 2) void qkv_kernel(
    const float* __restrict__ x, const float* __restrict__ w,
    const float* __restrict__ bq, const float* __restrict__ tau)
{
    __shared__ float As[GBK * GBM];   // [k][m]
    __shared__ float Bs[GBK * BNP];   // [k][n+pad]

    const int tid = threadIdx.x;
    const int tx = tid & 15;
    const int ty = tid >> 4;
    const int m0 = blockIdx.y * GBM;
    const int n0 = blockIdx.x * GBN;
    const int b  = m0 >> 8;           // 128 | 256: tile inside one batch
    const int t0 = m0 & (TT - 1);
    const float* xb = x + (size_t)b * CC * TT;

    float acc[8][8];
#pragma unroll
    for (int i = 0; i < 8; i++)
#pragma unroll
        for (int j = 0; j < 8; j++) acc[i][j] = 0.0f;

    for (int k0 = 0; k0 < CC; k0 += GBK) {
        // A: 16(k) x 128(t), float4 along t
#pragma unroll
        for (int s = 0; s < 2; s++) {
            int item = tid + s * 256;
            int kk = item >> 5;
            int t4 = item & 31;
            float4 v4 = *(const float4*)(xb + (size_t)(k0 + kk) * TT + t0 + t4 * 4);
            *(float4*)(As + kk * GBM + t4 * 4) = v4;
        }
        // B: 128(n) x 16(k): float4 along k, transposed store
#pragma unroll
        for (int s = 0; s < 2; s++) {
            int item = tid + s * 256;
            int n  = item >> 2;
            int kq = item & 3;
            float4 v4 = *(const float4*)(w + (size_t)(n0 + n) * CC + k0 + kq * 4);
            Bs[(kq * 4 + 0) * BNP + n] = v4.x;
            Bs[(kq * 4 + 1) * BNP + n] = v4.y;
            Bs[(kq * 4 + 2) * BNP + n] = v4.z;
            Bs[(kq * 4 + 3) * BNP + n] = v4.w;
        }
        __syncthreads();

#pragma unroll
        for (int k = 0; k < GBK; k++) {
            float4 a0 = *(const float4*)(As + k * GBM + tx * 4);
            float4 a1 = *(const float4*)(As + k * GBM + tx * 4 + 64);
            float4 b0 = *(const float4*)(Bs + k * BNP + ty * 4);
            float4 b1 = *(const float4*)(Bs + k * BNP + ty * 4 + 64);
            float ar[8] = {a0.x, a0.y, a0.z, a0.w, a1.x, a1.y, a1.z, a1.w};
            float br[8] = {b0.x, b0.y, b0.z, b0.w, b1.x, b1.y, b1.z, b1.w};
#pragma unroll
            for (int i = 0; i < 8; i++)
#pragma unroll
                for (int j = 0; j < 8; j++)
                    acc[i][j] = fmaf(ar[i], br[j], acc[i][j]);
        }
        __syncthreads();
    }

    // Epilogue: scatter into g_q / g_k / g_v [b][h][t][d]; pre-scale q rows.
#pragma unroll
    for (int g = 0; g < 2; g++) {                 // column half
        const int oc0 = n0 + ty * 4 + g * 64;
        const int s   = oc0 >> 8;                 // 0=q 1=k 2=v
        const int ch  = oc0 & (CC - 1);
        const int h   = ch >> 5;
        const int d0  = ch & (HD - 1);
        float4 bb = *(const float4*)(bq + oc0);
        float* dst = ((s == 0) ? g_q : (s == 1) ? g_k : g_v)
                   + (((size_t)b * NH + h) * TT) * HD + d0;
#pragma unroll
        for (int i = 0; i < 8; i++) {
            int t = t0 + tx * 4 + (i >> 2) * 64 + (i & 3);
            float4 o;
            o.x = acc[i][g * 4 + 0] + bb.x;
            o.y = acc[i][g * 4 + 1] + bb.y;
            o.z = acc[i][g * 4 + 2] + bb.z;
            o.w = acc[i][g * 4 + 3] + bb.w;
            *(float4*)(dst + (size_t)t * HD) = o;
        }
    }
}

// Post-pass: scale each q row by rsqrt(|q|^2)/tau (separate tiny kernel so the
// full row exists; one warp lane group per row-chunk).
__global__ __launch_bounds__(256) void qscale_kernel(const float* __restrict__ tau)
{
    // one thread per q row: 2048 * 256 rows / ... -> rows = BB*NH*TT = 524288
    int row = blockIdx.x * 256 + threadIdx.x;
    int h = (row >> 8) & (NH - 1);
    float* qr = g_q + (size_t)row * HD;
    float4 v[8];
    float s2 = 0.0f;
#pragma unroll
    for (int i = 0; i < 8; i++) {
        v[i] = *(const float4*)(qr + i * 4);
        s2 = fmaf(v[i].x, v[i].x, s2);
        s2 = fmaf(v[i].y, v[i].y, s2);
        s2 = fmaf(v[i].z, v[i].z, s2);
        s2 = fmaf(v[i].w, v[i].w, s2);
    }
    float sc = rsqrtf(fmaxf(s2, 1e-12f)) / fmaxf(tau[h], 0.01f);
#pragma unroll
    for (int i = 0; i < 8; i++) {
        v[i].x *= sc; v[i].y *= sc; v[i].z *= sc; v[i].w *= sc;
        *(float4*)(qr + i * 4) = v[i];
    }
}

// ---------------------------------------------------------------------------
// Kernel 3: attention.  One block per (b,h); 128 threads, 2 queries/thread.
// q pre-scaled; sc = dot * ikn[key] + bias.  Online softmax with branch.
// ---------------------------------------------------------------------------
#define KSTAGE 128
#define KP     36

__global__ __launch_bounds__(128, 2) void attn_kernel()
{
    __shared__ float ks[KSTAGE * KP];
    __shared__ float vs[KSTAGE * KP];
    __shared__ float ikn[KSTAGE];

    const int tid = threadIdx.x;
    const int bh  = blockIdx.x;
    const int b   = bh >> 3;
    const int h   = bh & 7;
    const size_t base = (size_t)bh * TT * HD;

    float q0[HD], q1[HD], a0[HD], a1[HD];
    {
        const float4* qr0 = (const float4*)(g_q + base + (size_t)tid * HD);
        const float4* qr1 = (const float4*)(g_q + base + (size_t)(tid + 128) * HD);
#pragma unroll
        for (int i = 0; i < 8; i++) {
            float4 t4 = qr0[i];
            q0[4*i+0] = t4.x; q0[4*i+1] = t4.y; q0[4*i+2] = t4.z; q0[4*i+3] = t4.w;
            float4 u4 = qr1[i];
            q1[4*i+0] = u4.x; q1[4*i+1] = u4.y; q1[4*i+2] = u4.z; q1[4*i+3] = u4.w;
        }
    }
#pragma unroll
    for (int d = 0; d < HD; d++) { a0[d] = 0.0f; a1[d] = 0.0f; }

    const float* brow0 = g_biasT + (size_t)h * TT * TT + tid;
    const float* brow1 = brow0 + 128;

    float m0 = -1e30f, l0 = 0.0f;
    float m1 = -1e30f, l1 = 0.0f;

    for (int j0 = 0; j0 < TT; j0 += KSTAGE) {
        __syncthreads();
        const float4* kg4 = (const float4*)(g_k + base + (size_t)j0 * HD);
        const float4* vg4 = (const float4*)(g_v + base + (size_t)j0 * HD);
#pragma unroll
        for (int it = 0; it < 8; it++) {
            int i = tid + it * 128;
            int r = i >> 3, c = i & 7;
            *(float4*)(ks + r * KP + c * 4) = kg4[i];
            *(float4*)(vs + r * KP + c * 4) = vg4[i];
        }
        __syncthreads();
        {
            float s2 = 0.0f;
#pragma unroll
            for (int d = 0; d < HD; d++) {
                float kv = ks[tid * KP + d];
                s2 = fmaf(kv, kv, s2);
            }
            ikn[tid] = rsqrtf(fmaxf(s2, 1e-12f));
        }
        __syncthreads();

        for (int j = 0; j < KSTAGE; j++) {
            const float4* kr = (const float4*)(ks + j * KP);
            float p00 = 0.f, p01 = 0.f, p02 = 0.f, p03 = 0.f;
            float p10 = 0.f, p11 = 0.f, p12 = 0.f, p13 = 0.f;
#pragma unroll
            for (int d4 = 0; d4 < 8; d4++) {
                float4 kv = kr[d4];
                p00 = fmaf(q0[4*d4+0], kv.x, p00);
                p01 = fmaf(q0[4*d4+1], kv.y, p01);
                p02 = fmaf(q0[4*d4+2], kv.z, p02);
                p03 = fmaf(q0[4*d4+3], kv.w, p03);
                p10 = fmaf(q1[4*d4+0], kv.x, p10);
                p11 = fmaf(q1[4*d4+1], kv.y, p11);
                p12 = fmaf(q1[4*d4+2], kv.z, p12);
                p13 = fmaf(q1[4*d4+3], kv.w, p13);
            }
            float ik = ikn[j];
            float sc0 = fmaf(((p00 + p01) + (p02 + p03)), ik, brow0[(size_t)(j0 + j) * TT]);
            float sc1 = fmaf(((p10 + p11) + (p12 + p13)), ik, brow1[(size_t)(j0 + j) * TT]);

            float4 vv[8];
            const float4* vr = (const float4*)(vs + j * KP);
#pragma unroll
            for (int d4 = 0; d4 < 8; d4++) vv[d4] = vr[d4];

            if (sc0 > m0) {
                float r = __expf(m0 - sc0);
                m0 = sc0;
                l0 = fmaf(l0, r, 1.0f);
#pragma unroll
                for (int d4 = 0; d4 < 8; d4++) {
                    a0[4*d4+0] = fmaf(a0[4*d4+0], r, vv[d4].x);
                    a0[4*d4+1] = fmaf(a0[4*d4+1], r, vv[d4].y);
                    a0[4*d4+2] = fmaf(a0[4*d4+2], r, vv[d4].z);
                    a0[4*d4+3] = fmaf(a0[4*d4+3], r, vv[d4].w);
                }
            } else {
                float p = __expf(sc0 - m0);
                l0 += p;
#pragma unroll
                for (int d4 = 0; d4 < 8; d4++) {
                    a0[4*d4+0] = fmaf(p, vv[d4].x, a0[4*d4+0]);
                    a0[4*d4+1] = fmaf(p, vv[d4].y, a0[4*d4+1]);
                    a0[4*d4+2] = fmaf(p, vv[d4].z, a0[4*d4+2]);
                    a0[4*d4+3] = fmaf(p, vv[d4].w, a0[4*d4+3]);
                }
            }
            if (sc1 > m1) {
                float r = __expf(m1 - sc1);
                m1 = sc1;
                l1 = fmaf(l1, r, 1.0f);
#pragma unroll
                for (int d4 = 0; d4 < 8; d4++) {
                    a1[4*d4+0] = fmaf(a1[4*d4+0], r, vv[d4].x);
                    a1[4*d4+1] = fmaf(a1[4*d4+1], r, vv[d4].y);
                    a1[4*d4+2] = fmaf(a1[4*d4+2], r, vv[d4].z);
                    a1[4*d4+3] = fmaf(a1[4*d4+3], r, vv[d4].w);
                }
            } else {
                float p = __expf(sc1 - m1);
                l1 += p;
#pragma unroll
                for (int d4 = 0; d4 < 8; d4++) {
                    a1[4*d4+0] = fmaf(p, vv[d4].x, a1[4*d4+0]);
                    a1[4*d4+1] = fmaf(p, vv[d4].y, a1[4*d4+1]);
                    a1[4*d4+2] = fmaf(p, vv[d4].z, a1[4*d4+2]);
                    a1[4*d4+3] = fmaf(p, vv[d4].w, a1[4*d4+3]);
                }
            }
        }
    }

    const float il0 = 1.0f / l0;
    const float il1 = 1.0f / l1;
    float* ob0 = g_ao + ((size_t)b * CC + h * HD) * TT + tid;
    float* ob1 = ob0 + 128;
#pragma unroll
    for (int d = 0; d < HD; d++) {
        ob0[(size_t)d * TT] = a0[d] * il0;
        ob1[(size_t)d * TT] = a1[d] * il1;
    }
}

// ---------------------------------------------------------------------------
// Kernel 4: proj GEMM.  out[b,co,t] = sum_ci ao[b,ci,t]*w[co,ci] + b[co]
// ---------------------------------------------------------------------------
__global__ __launch_bounds__(256, 2) void proj_kernel(
    const float* __restrict__ w, const float* __restrict__ bp,
    float* __restrict__ out)
{
    __shared__ float As[GBK * GBM];
    __shared__ float Bs[GBK * BNP];

    const int tid = threadIdx.x;
    const int tx = tid & 15;
    const int ty = tid >> 4;
    const int m0 = blockIdx.y * GBM;
    const int n0 = blockIdx.x * GBN;
    const int b  = m0 >> 8;
    const int t0 = m0 & (TT - 1);
    const float* ab = g_ao + (size_t)b * CC * TT;

    float acc[8][8];
#pragma unroll
    for (int i = 0; i < 8; i++)
#pragma unroll
        for (int j = 0; j < 8; j++) acc[i][j] = 0.0f;

    for (int k0 = 0; k0 < CC; k0 += GBK) {
#pragma unroll
        for (int s = 0; s < 2; s++) {
            int item = tid + s * 256;
            int kk = item >> 5;
            int t4 = item & 31;
            float4 v4 = *(const float4*)(ab + (size_t)(k0 + kk) * TT + t0 + t4 * 4);
            *(float4*)(As + kk * GBM + t4 * 4) = v4;
        }
#pragma unroll
        for (int s = 0; s < 2; s++) {
            int item = tid + s * 256;
            int n  = item >> 2;
            int kq = item & 3;
            float4 v4 = *(const float4*)(w + (size_t)(n0 + n) * CC + k0 + kq * 4);
            Bs[(kq * 4 + 0) * BNP + n] = v4.x;
            Bs[(kq * 4 + 1) * BNP + n] = v4.y;
            Bs[(kq * 4 + 2) * BNP + n] = v4.z;
            Bs[(kq * 4 + 3) * BNP + n] = v4.w;
        }
        __syncthreads();

#pragma unroll
        for (int k = 0; k < GBK; k++) {
            float4 a0 = *(const float4*)(As + k * GBM + tx * 4);
            float4 a1 = *(const float4*)(As + k * GBM + tx * 4 + 64);
            float4 b0 = *(const float4*)(Bs + k * BNP + ty * 4);
            float4 b1 = *(const float4*)(Bs + k * BNP + ty * 4 + 64);
            float ar[8] = {a0.x, a0.y, a0.z, a0.w, a1.x, a1.y, a1.z, a1.w};
            float br[8] = {b0.x, b0.y, b0.z, b0.w, b1.x, b1.y, b1.z, b1.w};
#pragma unroll
            for (int i = 0; i < 8; i++)
#pragma unroll
                for (int j = 0; j < 8; j++)
                    acc[i][j] = fmaf(ar[i], br[j], acc[i][j]);
        }
        __syncthreads();
    }

    // out[b][n][t]: float4 along t
#pragma unroll
    for (int g = 0; g < 2; g++) {
#pragma unroll
        for (int j = 0; j < 4; j++) {
            int n = n0 + ty * 4 + g * 64 + j;
            float bpv = bp[n];
            float4 o;
            o.x = acc[0][g*4+j] + bpv;
            o.y = acc[1][g*4+j] + bpv;
            o.z = acc[2][g*4+j] + bpv;
            o.w = acc[3][g*4+j] + bpv;
            *(float4*)(out + ((size_t)b * CC + n) * TT + t0 + tx * 4) = o;
            o.x = acc[4][g*4+j] + bpv;
            o.y = acc[5][g*4+j] + bpv;
            o.z = acc[6][g*4+j] + bpv;
            o.w = acc[7][g*4+j] + bpv;
            *(float4*)(out + ((size_t)b * CC + n) * TT + t0 + tx * 4 + 64) = o;
        }
    }
}

// ---------------------------------------------------------------------------
extern "C" void kernel_launch(void* const* d_in, const int* in_sizes, int n_in,
                              void* d_out, int out_size)
{
    const float* x      = (const float*)d_in[0];
    const float* w_qkv  = (const float*)d_in[1];
    const float* b_qkv  = (const float*)d_in[2];
    const float* w_proj = (const float*)d_in[3];
    const float* b_proj = (const float*)d_in[4];
    const float* mw1    = (const float*)d_in[5];
    const float* mb1    = (const float*)d_in[6];
    const float* mw2    = (const float*)d_in[7];
    const float* mb2    = (const float*)d_in[8];
    const float* tau    = (const float*)d_in[9];
    float* out = (float*)d_out;

    bias_kernel<<<TT * TT / 256, 256>>>(mw1, mb1, mw2, mb2);
    qkv_kernel<<<dim3(OC3 / GBN, BB * TT / GBM), 256>>>(x, w_qkv, b_qkv, tau);
    qscale_kernel<<<BB * NH * TT / 256, 256>>>(tau);
    attn_kernel<<<BB * NH, 128>>>();
    proj_kernel<<<dim3(CC / GBN, BB * TT / GBM), 256>>>(w_proj, b_proj, out);
}

// round 6
// speedup vs baseline: 1.5277x; 1.1872x over previous
#include <cuda_runtime.h>
#include <math.h>

#define BB   256   // batch
#define CC   256   // channels
#define TT   256   // tokens (16x16)
#define NH   8
#define HD   32
#define META 256
#define OC3  768

// ---------------- scratch (device globals; no runtime allocation) ----------
__device__ float g_q[(size_t)BB * NH * TT * HD];     // [b][h][t][d], scaled by 1/(|q| tau)
__device__ float g_k[(size_t)BB * NH * TT * HD];     // [b][h][t][d], scaled by 1/|k|
__device__ float g_v[(size_t)BB * NH * TT * HD];
__device__ float g_ao[(size_t)BB * CC * TT];         // [b][c][t]
__device__ float g_biasT[(size_t)NH * TT * TT];      // [h][key][query]
__device__ float g_biasMax[NH * TT];                 // max over key, per (h,query)

// ---------------------------------------------------------------------------
// Kernel 1: relative-position-bias MLP (transposed store: [h][key][query])
// ---------------------------------------------------------------------------
__global__ __launch_bounds__(256) void bias_kernel(
    const float* __restrict__ mw1, const float* __restrict__ mb1,
    const float* __restrict__ mw2, const float* __restrict__ mb2)
{
    __shared__ float s_w1[META * 2];
    __shared__ float s_b1[META];
    __shared__ float s_w2[NH * META];
    __shared__ float s_b2[NH];
    for (int i = threadIdx.x; i < META * 2; i += 256) s_w1[i] = mw1[i];
    for (int i = threadIdx.x; i < META;     i += 256) s_b1[i] = mb1[i];
    for (int i = threadIdx.x; i < NH * META; i += 256) s_w2[i] = mw2[i];
    if (threadIdx.x < NH) s_b2[threadIdx.x] = mb2[threadIdx.x];
    __syncthreads();

    int idx = blockIdx.x * 256 + threadIdx.x;   // idx = key*T + q  (q fast)
    int q  = idx & (TT - 1);
    int kk = idx >> 8;

    float d0 = (float)((q >> 4) - (kk >> 4));
    float d1 = (float)((q & 15) - (kk & 15));
    float r0 = copysignf(log1pf(fabsf(d0)), d0);
    float r1 = copysignf(log1pf(fabsf(d1)), d1);

    float acc[NH];
#pragma unroll
    for (int h = 0; h < NH; h++) acc[h] = s_b2[h];

    for (int j = 0; j < META; j++) {
        float hj = fmaf(r0, s_w1[2 * j], fmaf(r1, s_w1[2 * j + 1], s_b1[j]));
        hj = fmaxf(hj, 0.0f);
#pragma unroll
        for (int h = 0; h < NH; h++)
            acc[h] = fmaf(hj, s_w2[h * META + j], acc[h]);
    }
#pragma unroll
    for (int h = 0; h < NH; h++)
        g_biasT[(size_t)h * TT * TT + (size_t)kk * TT + q] = acc[h];
}

// Kernel 1b: per-(h,q) max over keys of the bias table.
__global__ __launch_bounds__(256) void biasmax_kernel()
{
    int h = blockIdx.x;
    int q = threadIdx.x;
    const float* p = g_biasT + (size_t)h * TT * TT + q;
    float m = -1e30f;
#pragma unroll 8
    for (int k = 0; k < TT; k++)
        m = fmaxf(m, p[(size_t)k * TT]);
    g_biasMax[h * TT + q] = m;
}

// ---------------------------------------------------------------------------
// GEMM tiles: 128(m) x 128(n) x 16(k), 256 threads, 8x8 micro-tile
// ---------------------------------------------------------------------------
#define GBM 128
#define GBN 128
#define GBK 16
#define BNP 132

// Kernel 2: QKV GEMM.  qkv[b,t,oc] = sum_c x[b,c,t] * w[oc,c] + b[oc]
__global__ __launch_bounds__(256, 2) void qkv_kernel(
    const float* __restrict__ x, const float* __restrict__ w,
    const float* __restrict__ bq)
{
    __shared__ float As[GBK * GBM];   // [k][m]
    __shared__ float Bs[GBK * BNP];   // [k][n+pad]

    const int tid = threadIdx.x;
    const int tx = tid & 15;
    const int ty = tid >> 4;
    const int m0 = blockIdx.y * GBM;
    const int n0 = blockIdx.x * GBN;
    const int b  = m0 >> 8;
    const int t0 = m0 & (TT - 1);
    const float* xb = x + (size_t)b * CC * TT;

    float acc[8][8];
#pragma unroll
    for (int i = 0; i < 8; i++)
#pragma unroll
        for (int j = 0; j < 8; j++) acc[i][j] = 0.0f;

    for (int k0 = 0; k0 < CC; k0 += GBK) {
#pragma unroll
        for (int s = 0; s < 2; s++) {
            int item = tid + s * 256;
            int kk = item >> 5;
            int t4 = item & 31;
            float4 v4 = *(const float4*)(xb + (size_t)(k0 + kk) * TT + t0 + t4 * 4);
            *(float4*)(As + kk * GBM + t4 * 4) = v4;
        }
#pragma unroll
        for (int s = 0; s < 2; s++) {
            int item = tid + s * 256;
            int n  = item >> 2;
            int kq = item & 3;
            float4 v4 = *(const float4*)(w + (size_t)(n0 + n) * CC + k0 + kq * 4);
            Bs[(kq * 4 + 0) * BNP + n] = v4.x;
            Bs[(kq * 4 + 1) * BNP + n] = v4.y;
            Bs[(kq * 4 + 2) * BNP + n] = v4.z;
            Bs[(kq * 4 + 3) * BNP + n] = v4.w;
        }
        __syncthreads();

#pragma unroll
        for (int k = 0; k < GBK; k++) {
            float4 a0 = *(const float4*)(As + k * GBM + tx * 4);
            float4 a1 = *(const float4*)(As + k * GBM + tx * 4 + 64);
            float4 b0 = *(const float4*)(Bs + k * BNP + ty * 4);
            float4 b1 = *(const float4*)(Bs + k * BNP + ty * 4 + 64);
            float ar[8] = {a0.x, a0.y, a0.z, a0.w, a1.x, a1.y, a1.z, a1.w};
            float br[8] = {b0.x, b0.y, b0.z, b0.w, b1.x, b1.y, b1.z, b1.w};
#pragma unroll
            for (int i = 0; i < 8; i++)
#pragma unroll
                for (int j = 0; j < 8; j++)
                    acc[i][j] = fmaf(ar[i], br[j], acc[i][j]);
        }
        __syncthreads();
    }

#pragma unroll
    for (int g = 0; g < 2; g++) {
        const int oc0 = n0 + ty * 4 + g * 64;
        const int s   = oc0 >> 8;                 // 0=q 1=k 2=v
        const int ch  = oc0 & (CC - 1);
        const int h   = ch >> 5;
        const int d0  = ch & (HD - 1);
        float4 bb = *(const float4*)(bq + oc0);
        float* dst = ((s == 0) ? g_q : (s == 1) ? g_k : g_v)
                   + (((size_t)b * NH + h) * TT) * HD + d0;
#pragma unroll
        for (int i = 0; i < 8; i++) {
            int t = t0 + tx * 4 + (i >> 2) * 64 + (i & 3);
            float4 o;
            o.x = acc[i][g * 4 + 0] + bb.x;
            o.y = acc[i][g * 4 + 1] + bb.y;
            o.z = acc[i][g * 4 + 2] + bb.z;
            o.w = acc[i][g * 4 + 3] + bb.w;
            *(float4*)(dst + (size_t)t * HD) = o;
        }
    }
}

// Kernel 2b: normalize q rows by rsqrt(|q|^2)/tau and k rows by rsqrt(|k|^2).
#define NROWS (BB * NH * TT)
__global__ __launch_bounds__(256) void qkscale_kernel(const float* __restrict__ tau)
{
    int row = blockIdx.x * 256 + threadIdx.x;     // [0, 2*NROWS)
    int isq = (row < NROWS);
    int r   = isq ? row : row - NROWS;
    int h   = (r >> 8) & (NH - 1);
    float* p = (isq ? g_q : g_k) + (size_t)r * HD;
    float4 v[8];
    float s2 = 0.0f;
#pragma unroll
    for (int i = 0; i < 8; i++) {
        v[i] = *(const float4*)(p + i * 4);
        s2 = fmaf(v[i].x, v[i].x, s2);
        s2 = fmaf(v[i].y, v[i].y, s2);
        s2 = fmaf(v[i].z, v[i].z, s2);
        s2 = fmaf(v[i].w, v[i].w, s2);
    }
    float sc = rsqrtf(fmaxf(s2, 1e-12f));
    if (isq) sc /= fmaxf(tau[h], 0.01f);
#pragma unroll
    for (int i = 0; i < 8; i++) {
        v[i].x *= sc; v[i].y *= sc; v[i].z *= sc; v[i].w *= sc;
        *(float4*)(p + i * 4) = v[i];
    }
}

// ---------------------------------------------------------------------------
// Kernel 3: attention, branch-free fixed-shift softmax.
// One block per (b,h); 128 threads, 2 queries/thread.
// sc = dot(q_hat, k_hat) + bias;  p = exp(sc - M),  M = biasMax + 1/tau >= max sc.
// ---------------------------------------------------------------------------
#define KSTAGE 128
#define KP     36

__global__ __launch_bounds__(128, 2) void attn_kernel(const float* __restrict__ tau)
{
    __shared__ float ks[KSTAGE * KP];
    __shared__ float vs[KSTAGE * KP];

    const int tid = threadIdx.x;
    const int bh  = blockIdx.x;
    const int b   = bh >> 3;
    const int h   = bh & 7;
    const size_t base = (size_t)bh * TT * HD;

    float q0[HD], q1[HD], a0[HD], a1[HD];
    {
        const float4* qr0 = (const float4*)(g_q + base + (size_t)tid * HD);
        const float4* qr1 = (const float4*)(g_q + base + (size_t)(tid + 128) * HD);
#pragma unroll
        for (int i = 0; i < 8; i++) {
            float4 t4 = qr0[i];
            q0[4*i+0] = t4.x; q0[4*i+1] = t4.y; q0[4*i+2] = t4.z; q0[4*i+3] = t4.w;
            float4 u4 = qr1[i];
            q1[4*i+0] = u4.x; q1[4*i+1] = u4.y; q1[4*i+2] = u4.z; q1[4*i+3] = u4.w;
        }
    }
#pragma unroll
    for (int d = 0; d < HD; d++) { a0[d] = 0.0f; a1[d] = 0.0f; }

    const float inv_tau = 1.0f / fmaxf(tau[h], 0.01f);
    const float M0 = g_biasMax[h * TT + tid]       + inv_tau;
    const float M1 = g_biasMax[h * TT + tid + 128] + inv_tau;
    const float* brow0 = g_biasT + (size_t)h * TT * TT + tid;
    const float* brow1 = brow0 + 128;

    float l0 = 0.0f, l1 = 0.0f;

    for (int j0 = 0; j0 < TT; j0 += KSTAGE) {
        __syncthreads();
        const float4* kg4 = (const float4*)(g_k + base + (size_t)j0 * HD);
        const float4* vg4 = (const float4*)(g_v + base + (size_t)j0 * HD);
#pragma unroll
        for (int it = 0; it < 8; it++) {
            int i = tid + it * 128;
            int r = i >> 3, c = i & 7;
            *(float4*)(ks + r * KP + c * 4) = kg4[i];
            *(float4*)(vs + r * KP + c * 4) = vg4[i];
        }
        __syncthreads();

#pragma unroll 2
        for (int j = 0; j < KSTAGE; j++) {
            const float4* kr = (const float4*)(ks + j * KP);
            float p00 = 0.f, p01 = 0.f, p02 = 0.f, p03 = 0.f;
            float p10 = 0.f, p11 = 0.f, p12 = 0.f, p13 = 0.f;
#pragma unroll
            for (int d4 = 0; d4 < 8; d4++) {
                float4 kv = kr[d4];
                p00 = fmaf(q0[4*d4+0], kv.x, p00);
                p01 = fmaf(q0[4*d4+1], kv.y, p01);
                p02 = fmaf(q0[4*d4+2], kv.z, p02);
                p03 = fmaf(q0[4*d4+3], kv.w, p03);
                p10 = fmaf(q1[4*d4+0], kv.x, p10);
                p11 = fmaf(q1[4*d4+1], kv.y, p11);
                p12 = fmaf(q1[4*d4+2], kv.z, p12);
                p13 = fmaf(q1[4*d4+3], kv.w, p13);
            }
            float bias0 = brow0[(size_t)(j0 + j) * TT];
            float bias1 = brow1[(size_t)(j0 + j) * TT];
            float e0 = __expf(((p00 + p01) + (p02 + p03)) + (bias0 - M0));
            float e1 = __expf(((p10 + p11) + (p12 + p13)) + (bias1 - M1));
            l0 += e0;
            l1 += e1;

            const float4* vr = (const float4*)(vs + j * KP);
#pragma unroll
            for (int d4 = 0; d4 < 8; d4++) {
                float4 vv = vr[d4];
                a0[4*d4+0] = fmaf(e0, vv.x, a0[4*d4+0]);
                a0[4*d4+1] = fmaf(e0, vv.y, a0[4*d4+1]);
                a0[4*d4+2] = fmaf(e0, vv.z, a0[4*d4+2]);
                a0[4*d4+3] = fmaf(e0, vv.w, a0[4*d4+3]);
                a1[4*d4+0] = fmaf(e1, vv.x, a1[4*d4+0]);
                a1[4*d4+1] = fmaf(e1, vv.y, a1[4*d4+1]);
                a1[4*d4+2] = fmaf(e1, vv.z, a1[4*d4+2]);
                a1[4*d4+3] = fmaf(e1, vv.w, a1[4*d4+3]);
            }
        }
    }

    const float il0 = 1.0f / l0;
    const float il1 = 1.0f / l1;
    float* ob0 = g_ao + ((size_t)b * CC + h * HD) * TT + tid;
    float* ob1 = ob0 + 128;
#pragma unroll
    for (int d = 0; d < HD; d++) {
        ob0[(size_t)d * TT] = a0[d] * il0;
        ob1[(size_t)d * TT] = a1[d] * il1;
    }
}

// ---------------------------------------------------------------------------
// Kernel 4: proj GEMM.  out[b,co,t] = sum_ci ao[b,ci,t]*w[co,ci] + b[co]
// ---------------------------------------------------------------------------
__global__ __launch_bounds__(256, 2) void proj_kernel(
    const float* __restrict__ w, const float* __restrict__ bp,
    float* __restrict__ out)
{
    __shared__ float As[GBK * GBM];
    __shared__ float Bs[GBK * BNP];

    const int tid = threadIdx.x;
    const int tx = tid & 15;
    const int ty = tid >> 4;
    const int m0 = blockIdx.y * GBM;
    const int n0 = blockIdx.x * GBN;
    const int b  = m0 >> 8;
    const int t0 = m0 & (TT - 1);
    const float* ab = g_ao + (size_t)b * CC * TT;

    float acc[8][8];
#pragma unroll
    for (int i = 0; i < 8; i++)
#pragma unroll
        for (int j = 0; j < 8; j++) acc[i][j] = 0.0f;

    for (int k0 = 0; k0 < CC; k0 += GBK) {
#pragma unroll
        for (int s = 0; s < 2; s++) {
            int item = tid + s * 256;
            int kk = item >> 5;
            int t4 = item & 31;
            float4 v4 = *(const float4*)(ab + (size_t)(k0 + kk) * TT + t0 + t4 * 4);
            *(float4*)(As + kk * GBM + t4 * 4) = v4;
        }
#pragma unroll
        for (int s = 0; s < 2; s++) {
            int item = tid + s * 256;
            int n  = item >> 2;
            int kq = item & 3;
            float4 v4 = *(const float4*)(w + (size_t)(n0 + n) * CC + k0 + kq * 4);
            Bs[(kq * 4 + 0) * BNP + n] = v4.x;
            Bs[(kq * 4 + 1) * BNP + n] = v4.y;
            Bs[(kq * 4 + 2) * BNP + n] = v4.z;
            Bs[(kq * 4 + 3) * BNP + n] = v4.w;
        }
        __syncthreads();

#pragma unroll
        for (int k = 0; k < GBK; k++) {
            float4 a0 = *(const float4*)(As + k * GBM + tx * 4);
            float4 a1 = *(const float4*)(As + k * GBM + tx * 4 + 64);
            float4 b0 = *(const float4*)(Bs + k * BNP + ty * 4);
            float4 b1 = *(const float4*)(Bs + k * BNP + ty * 4 + 64);
            float ar[8] = {a0.x, a0.y, a0.z, a0.w, a1.x, a1.y, a1.z, a1.w};
            float br[8] = {b0.x, b0.y, b0.z, b0.w, b1.x, b1.y, b1.z, b1.w};
#pragma unroll
            for (int i = 0; i < 8; i++)
#pragma unroll
                for (int j = 0; j < 8; j++)
                    acc[i][j] = fmaf(ar[i], br[j], acc[i][j]);
        }
        __syncthreads();
    }

#pragma unroll
    for (int g = 0; g < 2; g++) {
#pragma unroll
        for (int j = 0; j < 4; j++) {
            int n = n0 + ty * 4 + g * 64 + j;
            float bpv = bp[n];
            float4 o;
            o.x = acc[0][g*4+j] + bpv;
            o.y = acc[1][g*4+j] + bpv;
            o.z = acc[2][g*4+j] + bpv;
            o.w = acc[3][g*4+j] + bpv;
            *(float4*)(out + ((size_t)b * CC + n) * TT + t0 + tx * 4) = o;
            o.x = acc[4][g*4+j] + bpv;
            o.y = acc[5][g*4+j] + bpv;
            o.z = acc[6][g*4+j] + bpv;
            o.w = acc[7][g*4+j] + bpv;
            *(float4*)(out + ((size_t)b * CC + n) * TT + t0 + tx * 4 + 64) = o;
        }
    }
}

// ---------------------------------------------------------------------------
extern "C" void kernel_launch(void* const* d_in, const int* in_sizes, int n_in,
                              void* d_out, int out_size)
{
    const float* x      = (const float*)d_in[0];
    const float* w_qkv  = (const float*)d_in[1];
    const float* b_qkv  = (const float*)d_in[2];
    const float* w_proj = (const float*)d_in[3];
    const float* b_proj = (const float*)d_in[4];
    const float* mw1    = (const float*)d_in[5];
    const float* mb1    = (const float*)d_in[6];
    const float* mw2    = (const float*)d_in[7];
    const float* mb2    = (const float*)d_in[8];
    const float* tau    = (const float*)d_in[9];
    float* out = (float*)d_out;

    bias_kernel<<<TT * TT / 256, 256>>>(mw1, mb1, mw2, mb2);
    biasmax_kernel<<<NH, 256>>>();
    qkv_kernel<<<dim3(OC3 / GBN, BB * TT / GBM), 256>>>(x, w_qkv, b_qkv);
    qkscale_kernel<<<2 * NROWS / 256, 256>>>(tau);
    attn_kernel<<<BB * NH, 128>>>(tau);
    proj_kernel<<<dim3(CC / GBN, BB * TT / GBM), 256>>>(w_proj, b_proj, out);
}